// round 16
// baseline (speedup 1.0000x reference)
#include <cuda_runtime.h>
#include <cuda_bf16.h>
#include <cstdint>

// ConvTranspose2d(64,64,k=3,s=1,p=0) fp32 via mma.sync bf16-split implicit GEMM.
// out[co][oy][ox] = sum_{ci,ky,kx} x[ci][oy-ky][ox-kx] * w[co][ci][ky][kx]
// No x prepass: A staged inline from NCHW through a smem transpose scratch.
// B operands read as pre-built mma fragments from global (g_wfrag).

#define HH    1024
#define WW    1024
#define OHH   1026
#define OWW   1026
#define CIN   64
#define COUT  64

// B fragments: [half 2][tap 9][sp 2][k4 4][ng 2][lane 32] uint4
__device__ uint4 g_wfrag[9216];

// ---------------- helpers ----------------
__device__ __forceinline__ uint32_t smem_u32(const void* p) {
    uint32_t a;
    asm("{ .reg .u64 t; cvta.to.shared.u64 t, %1; cvt.u32.u64 %0, t; }" : "=r"(a) : "l"(p));
    return a;
}
__device__ __forceinline__ void ldsm4(uint32_t r[4], uint32_t addr) {
    asm volatile("ldmatrix.sync.aligned.m8n8.x4.shared.b16 {%0,%1,%2,%3}, [%4];"
        : "=r"(r[0]), "=r"(r[1]), "=r"(r[2]), "=r"(r[3]) : "r"(addr));
}
__device__ __forceinline__ void mma16816(float d[4], const uint32_t a[4], const uint32_t b[2]) {
    asm volatile("mma.sync.aligned.m16n8k16.row.col.f32.bf16.bf16.f32 "
        "{%0,%1,%2,%3}, {%4,%5,%6,%7}, {%8,%9}, {%0,%1,%2,%3};"
        : "+f"(d[0]), "+f"(d[1]), "+f"(d[2]), "+f"(d[3])
        : "r"(a[0]), "r"(a[1]), "r"(a[2]), "r"(a[3]), "r"(b[0]), "r"(b[1]));
}
__device__ __forceinline__ uint32_t packsplit(float v) {
    __nv_bfloat16 h = __float2bfloat16(v);
    float lof = v - __bfloat162float(h);
    __nv_bfloat16 l = __float2bfloat16(lof);
    unsigned short hu = *reinterpret_cast<unsigned short*>(&h);
    unsigned short lu = *reinterpret_cast<unsigned short*>(&l);
    return (uint32_t)hu | ((uint32_t)lu << 16);
}

// ---------------- Kernel 0: build B fragments ----------------
__global__ __launch_bounds__(256)
void wprep_kernel(const float* __restrict__ wgt)
{
    int i = blockIdx.x * 256 + threadIdx.x;
    if (i >= 9216) return;
    int lane = i & 31;
    int ng   = (i >> 5) & 1;
    int k4   = (i >> 6) & 3;
    int sp   = (i >> 8) & 1;
    int tap  = (i >> 9) % 9;
    int half = (i >> 9) / 9;
    int n    = lane >> 2;
    int kb   = k4 * 16 + (lane & 3) * 2;

    uint32_t r[4];
    #pragma unroll
    for (int nt = 0; nt < 2; nt++) {
        int co = half * 32 + ng * 16 + nt * 8 + n;
        #pragma unroll
        for (int bi = 0; bi < 2; bi++) {       // b0: k kb..kb+1, b1: kb+8..kb+9
            unsigned short us[2];
            #pragma unroll
            for (int j = 0; j < 2; j++) {
                int ci = kb + bi * 8 + j;
                float v = wgt[((size_t)co * CIN + ci) * 9 + tap];
                __nv_bfloat16 h = __float2bfloat16(v);
                float lof = v - __bfloat162float(h);
                __nv_bfloat16 l = __float2bfloat16(lof);
                __nv_bfloat16 pick = sp ? l : h;
                us[j] = *reinterpret_cast<unsigned short*>(&pick);
            }
            r[nt * 2 + bi] = (uint32_t)us[0] | ((uint32_t)us[1] << 16);
        }
    }
    g_wfrag[i] = make_uint4(r[0], r[1], r[2], r[3]);
}

// ---------------- Kernel 1: main ----------------
// smem: A ring 4 slots x {hi,lo} x 132 px-rows x 128B (16B-chunk XOR swizzle)
//       + scratch 64ci x 137 uint (hi|lo packed fp32-words)
#define ROWB    (132 * 128)                // 16896
#define ASLOT2  (2 * ROWB)                 // 33792
#define RING    (4 * ASLOT2)               // 135168
#define SC_STRIDE 137
#define SMEM_SZ (RING + CIN * SC_STRIDE * 4)   // 170240
#define BAND    27

// phase1: NCHW x row -> scratch (packed hi|lo), coalesced float2 reads
__device__ __forceinline__ void phase1(uint32_t* sc, const float* __restrict__ x,
                                       int y, int ox0, int tid)
{
    const bool yv = (unsigned)y < (unsigned)HH;
    #pragma unroll
    for (int k = 0; k < 9; k++) {
        int i = tid + k * 256;
        if (i < CIN * 33) {
            int ci = i / 33, g = i - ci * 33;
            int g0 = ox0 - 2 + 4 * g;
            float2 v01 = make_float2(0.f, 0.f), v23 = v01;
            if (yv) {
                const float* xp = x + (size_t)ci * (HH * WW) + (size_t)y * WW;
                if ((unsigned)g0 < (unsigned)WW)       v01 = *(const float2*)(xp + g0);
                if ((unsigned)(g0 + 2) < (unsigned)WW) v23 = *(const float2*)(xp + g0 + 2);
            }
            uint32_t* d = sc + ci * SC_STRIDE + 4 * g;
            d[0] = packsplit(v01.x); d[1] = packsplit(v01.y);
            d[2] = packsplit(v23.x); d[3] = packsplit(v23.y);
        }
    }
}

// phase2: scratch -> swizzled A ring (hi & lo planes), byte_perm repack
__device__ __forceinline__ void phase2(char* smem, uint32_t* sc, int y, int tid)
{
    const int slot = (y + 8) & 3;
    char* ah = smem + slot * ASLOT2;
    #pragma unroll
    for (int k = 0; k < 5; k++) {
        int i = tid + k * 256;
        if (i < 132 * 8) {
            int px = i >> 3, c = i & 7;
            uint32_t s_[8];
            #pragma unroll
            for (int j = 0; j < 8; j++)
                s_[j] = sc[(8 * c + j) * SC_STRIDE + px];
            uint4 hi = make_uint4(__byte_perm(s_[0], s_[1], 0x5410),
                                  __byte_perm(s_[2], s_[3], 0x5410),
                                  __byte_perm(s_[4], s_[5], 0x5410),
                                  __byte_perm(s_[6], s_[7], 0x5410));
            uint4 lo = make_uint4(__byte_perm(s_[0], s_[1], 0x7632),
                                  __byte_perm(s_[2], s_[3], 0x7632),
                                  __byte_perm(s_[4], s_[5], 0x7632),
                                  __byte_perm(s_[6], s_[7], 0x7632));
            uint32_t so = (uint32_t)(px * 128 + ((c ^ (px & 7)) << 4));
            *(uint4*)(ah + so)        = hi;
            *(uint4*)(ah + ROWB + so) = lo;
        }
    }
}

#define LOADF(AH, AL, BH, BL, K4) do {                                        \
    int _ch = 2 * (K4) + ach;                                                 \
    _Pragma("unroll")                                                         \
    for (int _mt = 0; _mt < 2; _mt++) {                                       \
        int _row = j0 + _mt * 16 + s + arow;                                  \
        uint32_t _off = (uint32_t)(_row * 128 + ((_ch ^ (_row & 7)) << 4));   \
        ldsm4(AH[_mt], ahb + _off);                                           \
        ldsm4(AL[_mt], alb + _off);                                           \
    }                                                                         \
    BH = __ldg(&g_wfrag[bidx + (K4) * 64]);                                   \
    BL = __ldg(&g_wfrag[bidx + 256 + (K4) * 64]);                             \
} while (0)

#define MMAF(AH, AL, BH, BL) do {                                             \
    uint32_t bh0[2] = {BH.x, BH.y}, bh1[2] = {BH.z, BH.w};                    \
    uint32_t bl0[2] = {BL.x, BL.y}, bl1[2] = {BL.z, BL.w};                    \
    _Pragma("unroll")                                                         \
    for (int _mt = 0; _mt < 2; _mt++) {                                       \
        mma16816(acc[_mt][0], AH[_mt], bh0);                                  \
        mma16816(acc[_mt][1], AH[_mt], bh1);                                  \
        mma16816(acc[_mt][0], AH[_mt], bl0);                                  \
        mma16816(acc[_mt][1], AH[_mt], bl1);                                  \
        mma16816(acc[_mt][0], AL[_mt], bh0);                                  \
        mma16816(acc[_mt][1], AL[_mt], bh1);                                  \
    }                                                                         \
} while (0)

__global__ __launch_bounds__(256, 1)
void convt_mma_kernel(const float* __restrict__ x, float* __restrict__ out)
{
    extern __shared__ char smem[];
    uint32_t* sc = (uint32_t*)(smem + RING);
    const uint32_t sb = smem_u32(smem);
    const int tid = threadIdx.x;
    const int wid = tid >> 5, lid = tid & 31;

    const int half = blockIdx.x;
    const int co0 = half * 32;
    const int ox0 = blockIdx.y * 128;
    const int oy0 = blockIdx.z * BAND;

    const int j0 = (wid & 3) * 32;    // warp px base (2 m-tiles of 16)
    const int n0 = (wid >> 2) * 16;   // warp co base (2 n-tiles of 8)

    const int arow = (lid & 7) + ((lid >> 3) & 1) * 8;   // A ldsm row-in-tile
    const int ach  = lid >> 4;                           // A k-half select
    const int base_bw = half * 4608 + (wid >> 2) * 32 + lid;  // B frag base

    // Prologue: rows oy0-2 .. oy0 into ring, oy0+1 into scratch
    phase1(sc, x, oy0 - 2, ox0, tid); __syncthreads();
    phase2(smem, sc, oy0 - 2, tid);   __syncthreads();
    phase1(sc, x, oy0 - 1, ox0, tid); __syncthreads();
    phase2(smem, sc, oy0 - 1, tid);   __syncthreads();
    phase1(sc, x, oy0,     ox0, tid); __syncthreads();
    phase2(smem, sc, oy0,   tid);     __syncthreads();
    phase1(sc, x, oy0 + 1, ox0, tid);

    for (int it = 0; it < BAND; it++) {
        const int oy = oy0 + it;
        __syncthreads();                           // phase1 STS + prev compute done
        if (it + 1 < BAND) phase2(smem, sc, oy + 1, tid);
        __syncthreads();                           // scratch reads done
        if (it + 2 < BAND) phase1(sc, x, oy + 2, ox0, tid);

        float acc[2][2][4];
        #pragma unroll
        for (int m = 0; m < 2; m++)
            #pragma unroll
            for (int n = 0; n < 2; n++)
                #pragma unroll
                for (int q = 0; q < 4; q++) acc[m][n][q] = 0.f;

        #pragma unroll
        for (int ky = 0; ky < 3; ky++) {
            const int slot = (oy - ky + 8) & 3;
            const uint32_t ahb = sb + slot * ASLOT2;
            const uint32_t alb = ahb + ROWB;
            #pragma unroll
            for (int kx = 0; kx < 3; kx++) {
                const int s = 2 - kx;
                const int bidx = base_bw + (ky * 3 + kx) * 512;

                uint32_t a0h[2][4], a0l[2][4], a1h[2][4], a1l[2][4];
                uint4 b0h, b0l, b1h, b1l;
                LOADF(a0h, a0l, b0h, b0l, 0);
                LOADF(a1h, a1l, b1h, b1l, 1);
                MMAF(a0h, a0l, b0h, b0l);
                LOADF(a0h, a0l, b0h, b0l, 2);
                MMAF(a1h, a1l, b1h, b1l);
                LOADF(a1h, a1l, b1h, b1l, 3);
                MMAF(a0h, a0l, b0h, b0l);
                MMAF(a1h, a1l, b1h, b1l);
            }
        }

        // Epilogue: direct fragment stores (32B-sector coalesced per quarter-warp)
        #pragma unroll
        for (int mt = 0; mt < 2; mt++)
            #pragma unroll
            for (int nt = 0; nt < 2; nt++) {
                int px = j0 + mt * 16 + (lid >> 2);
                int ox = ox0 + px;
                int co = co0 + n0 + nt * 8 + 2 * (lid & 3);
                float* bp = out + ((size_t)co * OHH + oy) * OWW + ox;
                const size_t cs = (size_t)OHH * OWW;
                if (ox < OWW)     { bp[0] = acc[mt][nt][0]; bp[cs] = acc[mt][nt][1]; }
                if (ox + 8 < OWW) { bp[8] = acc[mt][nt][2]; bp[cs + 8] = acc[mt][nt][3]; }
            }
    }
}

// ---------------- launch ----------------
extern "C" void kernel_launch(void* const* d_in, const int* in_sizes, int n_in,
                              void* d_out, int out_size)
{
    const float* x = (const float*)d_in[0];
    const float* w = (const float*)d_in[1];
    if (n_in >= 2 && in_sizes[0] < in_sizes[1]) {
        x = (const float*)d_in[1];
        w = (const float*)d_in[0];
    }
    float* out = (float*)d_out;

    cudaFuncSetAttribute(convt_mma_kernel,
                         cudaFuncAttributeMaxDynamicSharedMemorySize, SMEM_SZ);

    wprep_kernel<<<36, 256>>>(w);
    // 2 co-halves x 9 px-tiles x 38 bands of 27 rows (38*27 = 1026)
    convt_mma_kernel<<<dim3(COUT / 32, 9, OHH / BAND), 256, SMEM_SZ>>>(x, out);
}

// round 17
// speedup vs baseline: 1.6939x; 1.6939x over previous
#include <cuda_runtime.h>
#include <cuda_bf16.h>
#include <cstdint>

// ConvTranspose2d(64,64,k=3,s=1,p=0) fp32 via mma.sync bf16-split implicit GEMM.
// out[co][oy][ox] = sum_{ci,ky,kx} x[ci][oy-ky][ox-kx] * w[co][ci][ky][kx]

#define HH    1024
#define WW    1024
#define OHH   1026
#define OWW   1026
#define CIN   64
#define COUT  64

// scratch: pixel-major bf16 hi/lo split of x (device globals; no alloc APIs)
__device__ __nv_bfloat16 g_xt_hi[(size_t)HH * WW * CIN];
__device__ __nv_bfloat16 g_xt_lo[(size_t)HH * WW * CIN];

// ---------------- helpers ----------------
__device__ __forceinline__ uint32_t smem_u32(const void* p) {
    uint32_t a;
    asm("{ .reg .u64 t; cvta.to.shared.u64 t, %1; cvt.u32.u64 %0, t; }" : "=r"(a) : "l"(p));
    return a;
}
__device__ __forceinline__ void ldsm4(uint32_t r[4], uint32_t addr) {
    asm volatile("ldmatrix.sync.aligned.m8n8.x4.shared.b16 {%0,%1,%2,%3}, [%4];"
        : "=r"(r[0]), "=r"(r[1]), "=r"(r[2]), "=r"(r[3]) : "r"(addr));
}
__device__ __forceinline__ void mma16816(float d[4], const uint32_t a[4], const uint32_t b[2]) {
    asm volatile("mma.sync.aligned.m16n8k16.row.col.f32.bf16.bf16.f32 "
        "{%0,%1,%2,%3}, {%4,%5,%6,%7}, {%8,%9}, {%0,%1,%2,%3};"
        : "+f"(d[0]), "+f"(d[1]), "+f"(d[2]), "+f"(d[3])
        : "r"(a[0]), "r"(a[1]), "r"(a[2]), "r"(a[3]), "r"(b[0]), "r"(b[1]));
}

// ---------------- Kernel 1: transpose + hi/lo split (128-px tiles) ----------------
__global__ __launch_bounds__(512)
void prepass_kernel(const float* __restrict__ x)
{
    __shared__ float t[CIN * 129];
    const int tid = threadIdx.x;
    const int px0 = blockIdx.x * 128;
    const int y   = blockIdx.y;

    // 64 ci x 32 float4 = 2048 vec loads, 4 per thread (coalesced 512B/ci-row)
    #pragma unroll
    for (int k = 0; k < 4; k++) {
        int i = tid + k * 512;
        int ci = i >> 5, j = i & 31;
        float4 v = *(const float4*)(x + (size_t)ci * (HH * WW) + (size_t)y * WW + px0 + 4 * j);
        float* d = &t[ci * 129 + 4 * j];
        d[0] = v.x; d[1] = v.y; d[2] = v.z; d[3] = v.w;
    }
    __syncthreads();
    // 128 px x 8 chunks = 1024 writes, 2 per thread
    #pragma unroll
    for (int k = 0; k < 2; k++) {
        int i = tid + k * 512;
        int px = i >> 3, c = i & 7;
        __align__(16) __nv_bfloat16 h8[8], l8[8];
        #pragma unroll
        for (int j = 0; j < 8; j++) {
            float v = t[(c * 8 + j) * 129 + px];
            __nv_bfloat16 h = __float2bfloat16(v);
            h8[j] = h;
            l8[j] = __float2bfloat16(v - __bfloat162float(h));
        }
        size_t o = ((size_t)y * WW + px0 + px) * CIN + c * 8;
        *(uint4*)&g_xt_hi[o] = *(const uint4*)h8;
        *(uint4*)&g_xt_lo[o] = *(const uint4*)l8;
    }
}

// ---------------- Kernel 2: mma.sync main ----------------
// smem: A ring 4 slots x {hi,lo} x 132 px-rows x 128B (16B-chunk XOR swizzle),
//       B [tap 9][sp 2][co 32][128B ci] (chunk swizzle by co&7).
#define ROWB    (132 * 128)                // 16896 (one split plane of one slot)
#define ASLOT2  (2 * ROWB)                 // 33792 (hi+lo per slot)
#define OFF_B   (4 * ASLOT2)               // 135168
#define SMEM_SZ (OFF_B + 18 * 4096)        // 208896
#define BAND    27

// staging split: LDG->regs at iter start, STS at iter end (slot disjoint)
__device__ __forceinline__ void stage_ldg(uint4 vh[5], uint4 vl[5],
                                          int y, int ox0, int tid)
{
    const bool yv = (unsigned)y < (unsigned)HH;
    #pragma unroll
    for (int k = 0; k < 5; k++) {
        int i = tid + k * 256;
        uint4 a = make_uint4(0, 0, 0, 0), b = a;
        if (i < 132 * 8) {
            int px = i >> 3, c = i & 7;
            int gx = ox0 - 2 + px;
            if (yv && (unsigned)gx < (unsigned)WW) {
                size_t o = ((size_t)y * WW + gx) * CIN + c * 8;
                a = *(const uint4*)&g_xt_hi[o];
                b = *(const uint4*)&g_xt_lo[o];
            }
        }
        vh[k] = a; vl[k] = b;
    }
}
__device__ __forceinline__ void stage_sts(char* smem, const uint4 vh[5],
                                          const uint4 vl[5], int y, int tid)
{
    const int slot = (y + 8) & 3;
    char* ah = smem + slot * ASLOT2;
    #pragma unroll
    for (int k = 0; k < 5; k++) {
        int i = tid + k * 256;
        if (i < 132 * 8) {
            int px = i >> 3, c = i & 7;
            uint32_t so = (uint32_t)(px * 128 + ((c ^ (px & 7)) << 4));
            *(uint4*)(ah + so)        = vh[k];
            *(uint4*)(ah + ROWB + so) = vl[k];
        }
    }
}

// load all fragments for one k4 step (A hi/lo via ldsm, B hi/lo via ldsm)
#define LOADK(AH, AL, BH, BL, K4) do {                                         \
    _Pragma("unroll")                                                          \
    for (int _mt = 0; _mt < 2; _mt++) {                                        \
        int _row = j0 + _mt * 16 + s + arow;                                   \
        uint32_t _off = (uint32_t)(_row * 128 +                                \
                        (((2 * (K4) + ach) ^ (_row & 7)) << 4));               \
        ldsm4(AH[_mt], ahb + _off);                                            \
        ldsm4(AL[_mt], alb + _off);                                            \
    }                                                                          \
    {                                                                          \
        uint32_t _bo = (uint32_t)(brow * 128 +                                 \
                       (((2 * (K4) + bch) ^ (brow & 7)) << 4));                \
        ldsm4(BH, bhb + _bo);                                                  \
        ldsm4(BL, bhb + 4096 + _bo);                                           \
    }                                                                          \
} while (0)

#define MMAK(AH, AL, BH, BL) do {                                              \
    uint32_t _b0h[2] = {BH[0], BH[1]}, _b1h[2] = {BH[2], BH[3]};               \
    uint32_t _b0l[2] = {BL[0], BL[1]}, _b1l[2] = {BL[2], BL[3]};               \
    _Pragma("unroll")                                                          \
    for (int _mt = 0; _mt < 2; _mt++) {                                        \
        mma16816(acc[_mt][0], AH[_mt], _b0h);                                  \
        mma16816(acc[_mt][1], AH[_mt], _b1h);                                  \
        mma16816(acc[_mt][0], AH[_mt], _b0l);                                  \
        mma16816(acc[_mt][1], AH[_mt], _b1l);                                  \
        mma16816(acc[_mt][0], AL[_mt], _b0h);                                  \
        mma16816(acc[_mt][1], AL[_mt], _b1h);                                  \
    }                                                                          \
} while (0)

__global__ __launch_bounds__(256, 1)
void convt_mma_kernel(const float* __restrict__ wgt, float* __restrict__ out)
{
    extern __shared__ char smem[];
    const uint32_t sb = smem_u32(smem);
    const int tid = threadIdx.x;
    const int wid = tid >> 5, lid = tid & 31;

    const int co0 = blockIdx.x * 32;
    const int ox0 = blockIdx.y * 128;
    const int oy0 = blockIdx.z * BAND;

    // Stage weights: B[tap][sp][co][ci] bf16, chunk-swizzled 128B rows
    for (int i = tid; i < 9 * 32 * CIN; i += 256) {
        int ci = i & 63, co = (i >> 6) & 31, tap = i >> 11;
        float v = wgt[((size_t)(co0 + co) * CIN + ci) * 9 + tap];
        __nv_bfloat16 h = __float2bfloat16(v);
        __nv_bfloat16 l = __float2bfloat16(v - __bfloat162float(h));
        uint32_t boff = (uint32_t)(co * 128 + (((ci >> 3) ^ (co & 7)) << 4) + ((ci & 7) << 1));
        *(__nv_bfloat16*)(smem + OFF_B + (tap * 2 + 0) * 4096 + boff) = h;
        *(__nv_bfloat16*)(smem + OFF_B + (tap * 2 + 1) * 4096 + boff) = l;
    }

    // Prologue rows (LDG+STS combined)
    uint4 vh[5], vl[5];
    stage_ldg(vh, vl, oy0 - 2, ox0, tid); stage_sts(smem, vh, vl, oy0 - 2, tid);
    stage_ldg(vh, vl, oy0 - 1, ox0, tid); stage_sts(smem, vh, vl, oy0 - 1, tid);
    stage_ldg(vh, vl, oy0,     ox0, tid); stage_sts(smem, vh, vl, oy0,     tid);

    const int j0 = (wid & 3) * 32;   // warp px base (2 m-tiles of 16)
    const int n0 = (wid >> 2) * 16;  // warp co base (2 n-tiles of 8)

    const int arow = (lid & 7) + ((lid >> 3) & 1) * 8;   // A ldsm row-in-tile
    const int ach  = lid >> 4;                           // A k-half select
    const int bm   = lid >> 3;                           // B ldsm matrix id
    const int brow = n0 + ((bm >> 1) << 3) + (lid & 7);  // B co row
    const int bch  = bm & 1;                             // B k-half select

    for (int it = 0; it < BAND; it++) {
        const int oy = oy0 + it;
        __syncthreads();                 // prev iter's STS visible; compute done
        const bool more = (it + 1 < BAND);
        if (more) stage_ldg(vh, vl, oy + 1, ox0, tid);   // stall hides under mma

        float acc[2][2][4];
        #pragma unroll
        for (int m = 0; m < 2; m++)
            #pragma unroll
            for (int n = 0; n < 2; n++)
                #pragma unroll
                for (int q = 0; q < 4; q++) acc[m][n][q] = 0.f;

        #pragma unroll
        for (int ky = 0; ky < 3; ky++) {
            const int slot = (oy - ky + 8) & 3;
            const uint32_t ahb = sb + slot * ASLOT2;
            const uint32_t alb = ahb + ROWB;
            #pragma unroll
            for (int kx = 0; kx < 3; kx++) {
                const int s = 2 - kx;
                const uint32_t bhb = sb + OFF_B + ((ky * 3 + kx) * 2) * 4096;

                uint32_t a0h[2][4], a0l[2][4], b0h[4], b0l[4];
                uint32_t a1h[2][4], a1l[2][4], b1h[4], b1l[4];
                LOADK(a0h, a0l, b0h, b0l, 0);
                LOADK(a1h, a1l, b1h, b1l, 1);
                MMAK(a0h, a0l, b0h, b0l);
                LOADK(a0h, a0l, b0h, b0l, 2);
                MMAK(a1h, a1l, b1h, b1l);
                LOADK(a1h, a1l, b1h, b1l, 3);
                MMAK(a0h, a0l, b0h, b0l);
                MMAK(a1h, a1l, b1h, b1l);
            }
        }

        // drain staged row into its (disjoint) ring slot before the next sync
        if (more) stage_sts(smem, vh, vl, oy + 1, tid);

        // Epilogue: direct fragment stores (32B-sector coalesced per quarter-warp)
        #pragma unroll
        for (int mt = 0; mt < 2; mt++)
            #pragma unroll
            for (int nt = 0; nt < 2; nt++) {
                int px = j0 + mt * 16 + (lid >> 2);
                int ox = ox0 + px;
                int co = co0 + n0 + nt * 8 + 2 * (lid & 3);
                float* bp = out + ((size_t)co * OHH + oy) * OWW + ox;
                const size_t cs = (size_t)OHH * OWW;
                if (ox < OWW)     { bp[0] = acc[mt][nt][0]; bp[cs] = acc[mt][nt][1]; }
                if (ox + 8 < OWW) { bp[8] = acc[mt][nt][2]; bp[cs + 8] = acc[mt][nt][3]; }
            }
    }
}

// ---------------- launch ----------------
extern "C" void kernel_launch(void* const* d_in, const int* in_sizes, int n_in,
                              void* d_out, int out_size)
{
    const float* x = (const float*)d_in[0];
    const float* w = (const float*)d_in[1];
    if (n_in >= 2 && in_sizes[0] < in_sizes[1]) {
        x = (const float*)d_in[1];
        w = (const float*)d_in[0];
    }
    float* out = (float*)d_out;

    cudaFuncSetAttribute(convt_mma_kernel,
                         cudaFuncAttributeMaxDynamicSharedMemorySize, SMEM_SZ);

    prepass_kernel<<<dim3(WW / 128, HH), 512>>>(x);
    // 2 co-halves x 9 px-tiles x 38 bands of 27 rows (38*27 = 1026)
    convt_mma_kernel<<<dim3(COUT / 32, 9, OHH / BAND), 256, SMEM_SZ>>>(w, out);
}